// round 2
// baseline (speedup 1.0000x reference)
#include <cuda_runtime.h>
#include <cuda_bf16.h>
#include <cstdint>

// out = (v_reset > 0.5) where v_reset = v*(1-spike1) is provably <= 0.5
// (if v > thr it resets to 0; else v <= thr; strict compare). Output is
// identically zero for all inputs -> pure 134MB zero-fill of d_out.
//
// R1: one 16B store/thread, 32768 blocks -> 20.2us, 6.65 TB/s, issue=21.7%.
// R2: 8 stores/thread (4096 blocks, ~3.5 waves), streaming stores, to cut
// wave-transition + per-block prologue overhead and push toward the LTS cap.

#define VEC_PER_THREAD 8

__global__ void __launch_bounds__(256) zero_fill_v4x8(float4* __restrict__ out,
                                                      long long n4) {
    // Block covers a contiguous 256*8 float4 = 32KB chunk; each iteration is
    // a fully-coalesced 4KB warp-contiguous slab.
    long long base = (long long)blockIdx.x * (256 * VEC_PER_THREAD) + threadIdx.x;
    const float4 z = make_float4(0.f, 0.f, 0.f, 0.f);
#pragma unroll
    for (int k = 0; k < VEC_PER_THREAD; k++) {
        long long i = base + (long long)k * 256;
        if (i < n4) __stcs(&out[i], z);
    }
}

__global__ void zero_fill_tail(float* __restrict__ out,
                               long long start, long long n) {
    long long i = start + (long long)blockIdx.x * blockDim.x + threadIdx.x;
    if (i < n) out[i] = 0.f;
}

extern "C" void kernel_launch(void* const* d_in, const int* in_sizes, int n_in,
                              void* d_out, int out_size) {
    (void)d_in; (void)in_sizes; (void)n_in;

    long long n = (long long)out_size;   // 33,554,432 floats
    long long n4 = n / 4;                // 8,388,608 float4

    const int threads = 256;
    long long per_block = (long long)threads * VEC_PER_THREAD;
    long long blocks = (n4 + per_block - 1) / per_block;   // 4096
    if (blocks > 0) {
        zero_fill_v4x8<<<(unsigned)blocks, threads>>>((float4*)d_out, n4);
    }

    long long rem_start = n4 * 4;
    if (n - rem_start > 0) {
        zero_fill_tail<<<1, 256>>>((float*)d_out, rem_start, n);
    }
}